// round 12
// baseline (speedup 1.0000x reference)
#include <cuda_runtime.h>

#define TDIM 512
#define NREC 256
#define NIN 10
#define NOUT 3
#define BATCH 1024
#define ROWS 8
#define RG 4                // rows per row-group
#define NB (BATCH/ROWS)     // 128 blocks
#define NT 256              // 8 warps, 2/SMSP; 2 row-groups x 128 threads
#define HALF 128
#define JS 128              // j rows cached in SMEM per column
#define WPAD 132            // padded row: conflict-free LDS.128
#define NSTREAM (JS/4)      // 32 packs of 4 j streamed from L2

typedef unsigned long long u64;

__device__ ulonglong2 g_Wst[NSTREAM * NREC];   // [kb][c]: W_rec[c][128+4kb..+3], 128 KB
__device__ float g_l2p[NB];
__device__ unsigned int g_ctr;

static __device__ __forceinline__ u64 pk(float a, float b){
    u64 r; asm("mov.b64 %0,{%1,%2};":"=l"(r):"f"(a),"f"(b)); return r;
}
static __device__ __forceinline__ u64 fm2(u64 a, u64 b, u64 c){
    u64 d; asm("fma.rn.f32x2 %0,%1,%2,%3;":"=l"(d):"l"(a),"l"(b),"l"(c)); return d;
}
static __device__ __forceinline__ float2 up(u64 v){
    float2 f; asm("mov.b64 {%0,%1},%2;":"=f"(f.x),"=f"(f.y):"l"(v)); return f;
}

__global__ void prep_kernel(const float* __restrict__ W){
    int c = threadIdx.x;   // 256 threads
    const ulonglong2* row = (const ulonglong2*)(W + c * NREC);
    #pragma unroll
    for (int k = 0; k < NSTREAM; k++)
        g_Wst[k * NREC + c] = row[JS/4 + k];
}

// de-phased GEMM halves as macros (no extended-lambda support in harness)
#define DO_LDS_HALF                                                        \
    _Pragma("unroll 4")                                                    \
    for (int i2 = 0; i2 < 32; i2++){                                       \
        int jb = (i2 + rot) & 31;                                          \
        ulonglong2 w0 = wA0[jb];                                           \
        ulonglong2 w1 = wA1[jb];                                           \
        _Pragma("unroll")                                                  \
        for (int i = 0; i < RG; i++){                                      \
            ulonglong2 rv = rr[(ro + i) * 64 + jb];                        \
            a0[i] = fm2(rv.x, w0.x, a0[i]);                                \
            a0[i] = fm2(rv.y, w0.y, a0[i]);                                \
            a1[i] = fm2(rv.x, w1.x, a1[i]);                                \
            a1[i] = fm2(rv.y, w1.y, a1[i]);                                \
        }                                                                  \
    }

#define DO_LDG_HALF                                                        \
    _Pragma("unroll 4")                                                    \
    for (int i2 = 0; i2 < 32; i2++){                                       \
        int kb = (i2 + rot) & 31;                                          \
        ulonglong2 w0 = gw[kb * NREC + c0];                                \
        ulonglong2 w1 = gw[kb * NREC + c1];                                \
        _Pragma("unroll")                                                  \
        for (int i = 0; i < RG; i++){                                      \
            ulonglong2 rv = rr[(ro + i) * 64 + 32 + kb];                   \
            a0[i] = fm2(rv.x, w0.x, a0[i]);                                \
            a0[i] = fm2(rv.y, w0.y, a0[i]);                                \
            a1[i] = fm2(rv.x, w1.x, a1[i]);                                \
            a1[i] = fm2(rv.y, w1.y, a1[i]);                                \
        }                                                                  \
    }

__global__ __launch_bounds__(NT, 1)
void rnn_kernel(const float* __restrict__ x,
                const float* __restrict__ noise,
                const float* __restrict__ W_in,
                const float* __restrict__ W_rec,
                const float* __restrict__ W_out,
                const float* __restrict__ b_out,
                const float* __restrict__ bias,
                float* __restrict__ out, int out_size)
{
    extern __shared__ float sm[];
    float* Wsm = sm;                          // [256 c][WPAD] j<128, 135 KB
    float* rT  = Wsm + NREC * WPAD;           // [2][ROWS][NREC] double-buffered
    float* WoS = rT + 2 * ROWS * NREC;        // [3][256]
    float* xb  = WoS + NOUT * NREC;           // [2][ROWS][12]

    const int tid = threadIdx.x;
    const int b0  = blockIdx.x * ROWS;
    const int g   = tid >> 7;                 // row-group: rows 4g..4g+3
    const int t   = tid & (HALF - 1);
    const int ro  = g * RG;
    const int c0  = t;
    const int c1  = t + HALF;
    const int wid = tid >> 5, lane = tid & 31;
    const int wq  = wid & 3;                  // warp index within row-group
    const int rot   = (wq & 1) * 16;          // rotation inside each 32-pack half
    const int order = (wq >> 1) & 1;          // which half first

    // ---- init SMEM ----
    for (int idx = tid; idx < NREC * JS; idx += NT){
        int cc = idx >> 7, j = idx & (JS - 1);
        Wsm[cc * WPAD + j] = W_rec[cc * NREC + j];
    }
    for (int idx = tid; idx < 2 * ROWS * NREC; idx += NT) rT[idx] = 0.f;
    for (int idx = tid; idx < NOUT * NREC; idx += NT) WoS[idx] = W_out[idx];
    if (tid < ROWS * NIN){
        int i = tid / NIN, k = tid % NIN;
        xb[i * 12 + k] = x[(size_t)(b0 + i) * TDIM * NIN + k];   // t=0 into buf 0
    }

    float win0[NIN], win1[NIN];
    #pragma unroll
    for (int k = 0; k < NIN; k++){
        win0[k] = W_in[c0 * NIN + k];
        win1[k] = W_in[c1 * NIN + k];
    }
    const float bs0 = bias[c0], bs1 = bias[c1];
    const float bo0 = b_out[0], bo1 = b_out[1], bo2 = b_out[2];

    float r0[RG], r1[RG];
    #pragma unroll
    for (int i = 0; i < RG; i++){ r0[i] = 0.f; r1[i] = 0.f; }

    float nz0[RG], nz1[RG];
    #pragma unroll
    for (int i = 0; i < RG; i++){
        size_t nb = (size_t)(b0 + ro + i) * TDIM * NREC;
        nz0[i] = noise[nb + c0];
        nz1[i] = noise[nb + c1];
    }
    double l2d = 0.0;
    __syncthreads();

    const ulonglong2* __restrict__ wA0 = (const ulonglong2*)(Wsm + c0 * WPAD);
    const ulonglong2* __restrict__ wA1 = (const ulonglong2*)(Wsm + c1 * WPAD);
    const ulonglong2* __restrict__ gw  = g_Wst;

    for (int ts = 0; ts < TDIM; ts++){
        const int cur = ts & 1, nxt = cur ^ 1;
        const float* rTc = rT + cur * ROWS * NREC;
        float*       rTn = rT + nxt * ROWS * NREC;
        const float* xbc = xb + cur * 96;
        float*       xbn = xb + nxt * 96;
        const ulonglong2* __restrict__ rr = (const ulonglong2*)rTc;  // [ROWS][64]

        // next-step noise prefetch first (DRAM latency hides under GEMM)
        float pn0[RG], pn1[RG];
        {
            int tn = (ts + 1 < TDIM) ? ts + 1 : ts;
            #pragma unroll
            for (int i = 0; i < RG; i++){
                size_t nb = ((size_t)(b0 + ro + i) * TDIM + tn) * NREC;
                pn0[i] = noise[nb + c0];
                pn1[i] = noise[nb + c1];
            }
        }

        u64 a0[RG], a1[RG];
        #pragma unroll
        for (int i = 0; i < RG; i++){ a0[i] = pk(0.f, 0.f); a1[i] = pk(0.f, 0.f); }

        // de-phased GEMM: warps differ in half order and 16-pack rotation
        if (order){ DO_LDG_HALF; DO_LDS_HALF; }
        else      { DO_LDS_HALF; DO_LDG_HALF; }

        // u = bias + noise + x @ W_in^T  (overlaps GEMM tail latency)
        float u0[RG], u1[RG];
        #pragma unroll
        for (int i = 0; i < RG; i++){ u0[i] = bs0 + nz0[i]; u1[i] = bs1 + nz1[i]; }
        #pragma unroll
        for (int i = 0; i < RG; i++){
            #pragma unroll
            for (int k = 0; k < NIN; k++){
                float xv = xbc[(ro + i) * 12 + k];
                u0[i] = fmaf(xv, win0[k], u0[i]);
                u1[i] = fmaf(xv, win1[k], u1[i]);
            }
        }
        #pragma unroll
        for (int i = 0; i < RG; i++){ nz0[i] = pn0[i]; nz1[i] = pn1[i]; }

        // r_new = 0.8 r + 0.2 relu(gemm + u)
        float ssum = 0.f;
        #pragma unroll
        for (int i = 0; i < RG; i++){
            float2 v0 = up(a0[i]);
            float2 v1 = up(a1[i]);
            float vv0 = (v0.x + v0.y) + u0[i];
            float vv1 = (v1.x + v1.y) + u1[i];
            r0[i] = 0.8f * r0[i] + 0.2f * fmaxf(vv0, 0.f);
            r1[i] = 0.8f * r1[i] + 0.2f * fmaxf(vv1, 0.f);
            rTn[(ro + i) * NREC + c0] = r0[i];
            rTn[(ro + i) * NREC + c1] = r1[i];
            ssum = fmaf(r0[i], r0[i], ssum);
            ssum = fmaf(r1[i], r1[i], ssum);
        }
        l2d += (double)ssum;

        // prefetch next x tile
        if (tid < ROWS * NIN){
            int i = tid / NIN, k = tid % NIN;
            int tn = (ts + 1 < TDIM) ? ts + 1 : ts;
            xbn[i * 12 + k] = x[((size_t)(b0 + i) * TDIM + tn) * NIN + k];
        }

        __syncthreads();   // single barrier per step

        // z = r_new @ W_out^T + b_out ; warp w -> batch row w
        {
            float z0 = 0.f, z1 = 0.f, z2 = 0.f;
            #pragma unroll
            for (int q = 0; q < NREC/32; q++){
                int jj = lane + 32 * q;
                float ra = rTn[wid * NREC + jj];
                z0 = fmaf(ra, WoS[jj],          z0);
                z1 = fmaf(ra, WoS[NREC + jj],   z1);
                z2 = fmaf(ra, WoS[2*NREC + jj], z2);
            }
            #pragma unroll
            for (int off = 16; off; off >>= 1){
                z0 += __shfl_down_sync(~0u, z0, off);
                z1 += __shfl_down_sync(~0u, z1, off);
                z2 += __shfl_down_sync(~0u, z2, off);
            }
            if (lane == 0){
                size_t ob = ((size_t)(b0 + wid) * TDIM + ts) * NOUT;
                out[ob+0] = z0 + bo0; out[ob+1] = z1 + bo1; out[ob+2] = z2 + bo2;
            }
        }
    }

    // ---- deterministic l2 reduction, last-block finalization ----
    __syncthreads();
    double* dd = (double*)sm;
    dd[tid] = l2d;
    __syncthreads();
    if (tid == 0){
        double s = 0.0;
        #pragma unroll 8
        for (int i = 0; i < NT; i++) s += dd[i];
        g_l2p[blockIdx.x] = (float)s;
        __threadfence();
        unsigned int old = atomicInc(&g_ctr, NB - 1);
        if (old == NB - 1){
            __threadfence();
            double tot = 0.0;
            for (int i = 0; i < NB; i++) tot += (double)g_l2p[i];
            out[out_size - 1] = (float)(tot / ((double)TDIM * BATCH * NREC));
        }
    }
}

extern "C" void kernel_launch(void* const* d_in, const int* in_sizes, int n_in,
                              void* d_out, int out_size)
{
    const float* x     = (const float*)d_in[0];
    const float* noise = (const float*)d_in[1];
    const float* W_in  = (const float*)d_in[2];
    const float* W_rec = (const float*)d_in[3];
    const float* W_out = (const float*)d_in[4];
    const float* b_out = (const float*)d_in[5];
    const float* bias  = (const float*)d_in[6];
    float* out = (float*)d_out;

    size_t smem = (size_t)(NREC*WPAD + 2*ROWS*NREC + NOUT*NREC + 2*96) * sizeof(float);
    cudaFuncSetAttribute(rnn_kernel, cudaFuncAttributeMaxDynamicSharedMemorySize, (int)smem);

    prep_kernel<<<1, 256>>>(W_rec);
    rnn_kernel<<<NB, NT, smem>>>(x, noise, W_in, W_rec, W_out, b_out, bias, out, out_size);
}

// round 15
// speedup vs baseline: 2.0525x; 2.0525x over previous
#include <cuda_runtime.h>
#include <cuda_bf16.h>
#include <cstdint>

#define TDIM 512
#define NREC 256
#define NIN 10
#define NOUT 3
#define BATCH 1024
#define ROWS 8
#define NB (BATCH/ROWS)     // 128 blocks
#define NT 256              // 8 warps; warp w owns m-tiles {2w, 2w+1}

// SMEM byte offsets
#define WHI_OFF  0          // Whi bf16 [256 m][256 k], 512B rows, XOR-swizzled
#define RB0H_OFF 131072     // r bf16 hi/lo, 2 buffers, [8 n][528B]
#define RB0L_OFF 135296
#define RB1H_OFF 139520
#define RB1L_OFF 143744
#define UD_OFF   147968     // u drive fp32 [8 n][260 words]
#define RT_OFF   156288     // r fp32 [8 n][256 m]
#define WOS_OFF  164480     // W_out [3][256]
#define XB_OFF   167552     // x staging [2][8][12]
#define SMEM_BYTES 168320

__device__ uint4 g_wlo[16*16*32];   // Wlo bf16 in A-fragment order, 128 KB
__device__ float g_l2p[NB];
__device__ unsigned int g_ctr;

static __device__ __forceinline__ uint32_t smem_u32(const void* p){
    uint32_t a; asm("{ .reg .u64 t; cvta.to.shared.u64 t, %1; cvt.u32.u64 %0, t; }":"=r"(a):"l"(p)); return a;
}
static __device__ __forceinline__ uint16_t bfu(float f){
    __nv_bfloat16 h = __float2bfloat16(f); return *(uint16_t*)&h;
}
static __device__ __forceinline__ float bff(uint16_t u){
    __nv_bfloat16 h = *(__nv_bfloat16*)&u; return __bfloat162float(h);
}
static __device__ __forceinline__ void ldsm4(uint32_t* r, uint32_t addr){
    asm volatile("ldmatrix.sync.aligned.m8n8.x4.shared.b16 {%0,%1,%2,%3}, [%4];"
        : "=r"(r[0]),"=r"(r[1]),"=r"(r[2]),"=r"(r[3]) : "r"(addr));
}
static __device__ __forceinline__ void mma16816(float* d, const uint32_t* a, const uint32_t* b){
    asm volatile("mma.sync.aligned.m16n8k16.row.col.f32.bf16.bf16.f32 "
        "{%0,%1,%2,%3}, {%4,%5,%6,%7}, {%8,%9}, {%0,%1,%2,%3};"
        : "+f"(d[0]),"+f"(d[1]),"+f"(d[2]),"+f"(d[3])
        : "r"(a[0]),"r"(a[1]),"r"(a[2]),"r"(a[3]), "r"(b[0]),"r"(b[1]));
}
static __device__ __forceinline__ uint32_t lds32(uint32_t addr){
    uint32_t v; asm volatile("ld.shared.b32 %0, [%1];" : "=r"(v) : "r"(addr)); return v;
}

// one-time: Wlo (bf16 residual) in exact m16n8k16 A-fragment order
__global__ void prep_kernel(const float* __restrict__ W){
    int idx = blockIdx.x * 256 + threadIdx.x;     // 0..8191
    int t = idx >> 5, l = idx & 31;
    int mt = t >> 4, kt = t & 15;
    int g = l >> 2, c = l & 3;
    int m0 = mt * 16 + g, k0 = kt * 16 + c * 2;
    uint32_t r[4];
    #pragma unroll
    for (int q = 0; q < 4; q++){
        int m = m0 + ((q & 1) ? 8 : 0);
        int k = k0 + ((q & 2) ? 8 : 0);
        float w0 = W[m * NREC + k],  w1 = W[m * NREC + k + 1];
        uint16_t l0 = bfu(w0 - bff(bfu(w0)));
        uint16_t l1 = bfu(w1 - bff(bfu(w1)));
        r[q] = (uint32_t)l0 | ((uint32_t)l1 << 16);
    }
    g_wlo[idx] = make_uint4(r[0], r[1], r[2], r[3]);
}

__global__ __launch_bounds__(NT, 1)
void rnn_kernel(const float* __restrict__ x,
                const float* __restrict__ noise,
                const float* __restrict__ W_in,
                const float* __restrict__ W_rec,
                const float* __restrict__ W_out,
                const float* __restrict__ b_out,
                const float* __restrict__ bias,
                float* __restrict__ out, int out_size)
{
    extern __shared__ char sm[];
    const uint32_t sb = smem_u32(sm);
    float* udS = (float*)(sm + UD_OFF);
    float* rT  = (float*)(sm + RT_OFF);
    float* WoS = (float*)(sm + WOS_OFF);
    float* xb  = (float*)(sm + XB_OFF);

    const int tid = threadIdx.x;
    const int w = tid >> 5, l = tid & 31;
    const int g = l >> 2, c = l & 3;
    const int b0 = blockIdx.x * ROWS;

    // ---- init Whi in SMEM (bf16, swizzled) ----
    for (int i = tid; i < NREC * NREC; i += NT){
        int m = i >> 8, k = i & 255;
        uint16_t h = bfu(W_rec[m * NREC + k]);
        int k16 = k >> 3;
        uint32_t off = (uint32_t)m * 512 + (uint32_t)((k16 ^ (m & 7)) << 4) + (uint32_t)((k & 7) * 2);
        *(uint16_t*)(sm + WHI_OFF + off) = h;
    }
    // zero all r bf16 buffers (r_{-1} = 0)
    for (int i = tid; i < (4 * 4224) / 4; i += NT)
        *(uint32_t*)(sm + RB0H_OFF + i * 4) = 0;
    for (int i = tid; i < NOUT * NREC; i += NT) WoS[i] = W_out[i];
    if (tid < ROWS * NIN){
        int i = tid / NIN, k = tid % NIN;
        xb[i * 12 + k] = x[(size_t)(b0 + i) * TDIM * NIN + k];
    }

    float win[NIN];
    #pragma unroll
    for (int k = 0; k < NIN; k++) win[k] = W_in[tid * NIN + k];
    const float bsm = bias[tid];
    const float bo0 = b_out[0], bo1 = b_out[1], bo2 = b_out[2];

    float rold[8];
    #pragma unroll
    for (int s = 0; s < 8; s++) rold[s] = 0.f;
    double l2d = 0.0;

    // ldmatrix lane addressing
    const int rowL = l & 15, hiL = l >> 4, xrL = l & 7;
    uint32_t aBase[2];
    #pragma unroll
    for (int mtl = 0; mtl < 2; mtl++)
        aBase[mtl] = sb + WHI_OFF + (uint32_t)((32 * w + 16 * mtl + rowL) * 512);

    __syncthreads();

    const uint32_t rbH[2] = { sb + RB0H_OFF, sb + RB1H_OFF };
    const uint32_t rbL[2] = { sb + RB0L_OFF, sb + RB1L_OFF };

    for (int ts = 0; ts < TDIM; ts++){
        const int cur = ts & 1, nxt = cur ^ 1;
        const float* xbc = xb + cur * 96;
        float*       xbn = xb + nxt * 96;

        // ---- phase 1: noise for my 8 slots, u drive, next-x stage ----
        float nz[8];
        #pragma unroll
        for (int mtl = 0; mtl < 2; mtl++)
            #pragma unroll
            for (int j = 0; j < 4; j++){
                int mS = 32 * w + 16 * mtl + g + ((j >> 1) << 3);
                int nS = (c << 1) + (j & 1);
                nz[mtl * 4 + j] = noise[((size_t)(b0 + nS) * TDIM + ts) * NREC + mS];
            }
        #pragma unroll
        for (int n = 0; n < ROWS; n++){
            float u = bsm;
            #pragma unroll
            for (int k = 0; k < NIN; k++) u = fmaf(xbc[n * 12 + k], win[k], u);
            udS[n * 260 + tid] = u;
        }
        if (tid < ROWS * NIN){
            int i = tid / NIN, k = tid % NIN;
            int tn = (ts + 1 < TDIM) ? ts + 1 : ts;
            xbn[i * 12 + k] = x[((size_t)(b0 + i) * TDIM + tn) * NIN + k];
        }
        __syncthreads();   // barrier 1: ud visible; prev rbf writes visible

        // ---- phase 2: MMA pipeline over 16 k-tiles ----
        float d[2][4];
        #pragma unroll
        for (int mtl = 0; mtl < 2; mtl++)
            #pragma unroll
            for (int j = 0; j < 4; j++) d[mtl][j] = 0.f;

        const uint32_t bHbase = rbH[cur] + (uint32_t)((l >> 2) * 528 + (l & 3) * 4);
        const uint32_t bLbase = rbL[cur] + (uint32_t)((l >> 2) * 528 + (l & 3) * 4);

        uint4 alo[4][2];
        #pragma unroll
        for (int p = 0; p < 4; p++)
            #pragma unroll
            for (int mtl = 0; mtl < 2; mtl++)
                alo[p][mtl] = g_wlo[((2 * w + mtl) * 16 + p) * 32 + l];

        uint32_t bh[2][2], bl[2][2], ah[2][2][4];
        // preload kt = 0
        bh[0][0] = lds32(bHbase);
        bh[0][1] = lds32(bHbase + 16);
        bl[0][0] = lds32(bLbase);
        bl[0][1] = lds32(bLbase + 16);
        #pragma unroll
        for (int mtl = 0; mtl < 2; mtl++)
            ldsm4(ah[0][mtl], aBase[mtl] + (uint32_t)(((0 + hiL) ^ xrL) << 4));

        #pragma unroll
        for (int kt = 0; kt < 16; kt++){
            const int cb = kt & 1, nb = cb ^ 1;
            if (kt < 15){
                uint32_t bo = bHbase + (uint32_t)((kt + 1) * 32);
                bh[nb][0] = lds32(bo);
                bh[nb][1] = lds32(bo + 16);
                uint32_t bo2 = bLbase + (uint32_t)((kt + 1) * 32);
                bl[nb][0] = lds32(bo2);
                bl[nb][1] = lds32(bo2 + 16);
                #pragma unroll
                for (int mtl = 0; mtl < 2; mtl++)
                    ldsm4(ah[nb][mtl], aBase[mtl] + (uint32_t)(((2 * (kt + 1) + hiL) ^ xrL) << 4));
            }
            #pragma unroll
            for (int mtl = 0; mtl < 2; mtl++){
                mma16816(d[mtl], ah[cb][mtl], bh[cb]);                        // Whi*rhi
                mma16816(d[mtl], ah[cb][mtl], bl[cb]);                        // Whi*rlo
                mma16816(d[mtl], (const uint32_t*)&alo[kt & 3][mtl], bh[cb]); // Wlo*rhi
            }
            if (kt + 4 < 16){
                #pragma unroll
                for (int mtl = 0; mtl < 2; mtl++)
                    alo[kt & 3][mtl] = g_wlo[((2 * w + mtl) * 16 + (kt + 4)) * 32 + l];
            }
        }

        // ---- combine: r_new = 0.8 r + 0.2 relu(v + u + noise) ----
        float ssum = 0.f;
        #pragma unroll
        for (int mtl = 0; mtl < 2; mtl++)
            #pragma unroll
            for (int j = 0; j < 4; j++){
                int mS = 32 * w + 16 * mtl + g + ((j >> 1) << 3);
                int nS = (c << 1) + (j & 1);
                int s  = mtl * 4 + j;
                float v = d[mtl][j] + udS[nS * 260 + mS] + nz[s];
                float rn = 0.8f * rold[s] + 0.2f * fmaxf(v, 0.f);
                rold[s] = rn;
                uint16_t h  = bfu(rn);
                uint16_t lo = bfu(rn - bff(h));
                uint32_t ro = (uint32_t)(nS * 528 + mS * 2);
                *(uint16_t*)(sm + (rbH[nxt] - sb) + ro) = h;
                *(uint16_t*)(sm + (rbL[nxt] - sb) + ro) = lo;
                rT[nS * 256 + mS] = rn;
                ssum = fmaf(rn, rn, ssum);
            }
        l2d += (double)ssum;

        __syncthreads();   // barrier 2: rT + rbf[nxt] published

        // ---- phase 3: z epilogue, warp w -> batch row w ----
        {
            float z0 = 0.f, z1 = 0.f, z2 = 0.f;
            #pragma unroll
            for (int q = 0; q < NREC / 32; q++){
                int m = l + 32 * q;
                float ra = rT[w * 256 + m];
                z0 = fmaf(ra, WoS[m],        z0);
                z1 = fmaf(ra, WoS[256 + m],  z1);
                z2 = fmaf(ra, WoS[512 + m],  z2);
            }
            #pragma unroll
            for (int off = 16; off; off >>= 1){
                z0 += __shfl_down_sync(~0u, z0, off);
                z1 += __shfl_down_sync(~0u, z1, off);
                z2 += __shfl_down_sync(~0u, z2, off);
            }
            if (l == 0){
                size_t ob = ((size_t)(b0 + w) * TDIM + ts) * NOUT;
                out[ob + 0] = z0 + bo0; out[ob + 1] = z1 + bo1; out[ob + 2] = z2 + bo2;
            }
        }
    }

    // ---- deterministic l2 reduction, last-block finalization ----
    __syncthreads();
    double* dd = (double*)(sm + UD_OFF);
    dd[tid] = l2d;
    __syncthreads();
    if (tid == 0){
        double s = 0.0;
        for (int i = 0; i < NT; i++) s += dd[i];
        g_l2p[blockIdx.x] = (float)s;
        __threadfence();
        unsigned int old = atomicInc(&g_ctr, NB - 1);
        if (old == NB - 1){
            __threadfence();
            double tot = 0.0;
            for (int i = 0; i < NB; i++) tot += (double)g_l2p[i];
            out[out_size - 1] = (float)(tot / ((double)TDIM * BATCH * NREC));
        }
    }
}

extern "C" void kernel_launch(void* const* d_in, const int* in_sizes, int n_in,
                              void* d_out, int out_size)
{
    const float* x     = (const float*)d_in[0];
    const float* noise = (const float*)d_in[1];
    const float* W_in  = (const float*)d_in[2];
    const float* W_rec = (const float*)d_in[3];
    const float* W_out = (const float*)d_in[4];
    const float* b_out = (const float*)d_in[5];
    const float* bias  = (const float*)d_in[6];
    float* out = (float*)d_out;

    cudaFuncSetAttribute(rnn_kernel, cudaFuncAttributeMaxDynamicSharedMemorySize, SMEM_BYTES);
    prep_kernel<<<32, 256>>>(W_rec);
    rnn_kernel<<<NB, NT, SMEM_BYTES>>>(x, noise, W_in, W_rec, W_out, b_out, bias, out, out_size);
}

// round 16
// speedup vs baseline: 2.5078x; 1.2218x over previous
#include <cuda_runtime.h>
#include <cuda_bf16.h>
#include <cstdint>

#define TDIM 512
#define NREC 256
#define NIN 10
#define NOUT 3
#define BATCH 1024
#define ROWS 8
#define NB (BATCH/ROWS)     // 128 blocks
#define NT 256              // 8 warps; warp w owns m-tiles {2w, 2w+1}

// SMEM byte offsets
#define WHI_OFF  0          // Whi bf16 [256 m][256 k], 512B rows, XOR-swizzled
#define RB0H_OFF 131072     // r bf16 hi/lo, 2 buffers, [8 n][528B]
#define RB0L_OFF 135296
#define RB1H_OFF 139520
#define RB1L_OFF 143744
#define UD_OFF   147968     // u drive fp32 [8 n][260 words] (bias + xWin + noise)
#define WOS_OFF  156288     // W_out [3][256]
#define XB_OFF   159360     // x staging [2][8][12]
#define SMEM_BYTES 160256

__device__ uint4 g_wlo[16*16*32];   // Wlo bf16 in A-fragment order, 128 KB
__device__ float g_l2p[NB];
__device__ unsigned int g_ctr;

static __device__ __forceinline__ uint32_t smem_u32(const void* p){
    uint32_t a; asm("{ .reg .u64 t; cvta.to.shared.u64 t, %1; cvt.u32.u64 %0, t; }":"=r"(a):"l"(p)); return a;
}
static __device__ __forceinline__ uint16_t bfu(float f){
    __nv_bfloat16 h = __float2bfloat16(f); return *(uint16_t*)&h;
}
static __device__ __forceinline__ float bff(uint16_t u){
    __nv_bfloat16 h = *(__nv_bfloat16*)&u; return __bfloat162float(h);
}
static __device__ __forceinline__ void ldsm4(uint32_t* r, uint32_t addr){
    asm volatile("ldmatrix.sync.aligned.m8n8.x4.shared.b16 {%0,%1,%2,%3}, [%4];"
        : "=r"(r[0]),"=r"(r[1]),"=r"(r[2]),"=r"(r[3]) : "r"(addr));
}
static __device__ __forceinline__ void mma16816(float* d, const uint32_t* a, const uint32_t* b){
    asm volatile("mma.sync.aligned.m16n8k16.row.col.f32.bf16.bf16.f32 "
        "{%0,%1,%2,%3}, {%4,%5,%6,%7}, {%8,%9}, {%0,%1,%2,%3};"
        : "+f"(d[0]),"+f"(d[1]),"+f"(d[2]),"+f"(d[3])
        : "r"(a[0]),"r"(a[1]),"r"(a[2]),"r"(a[3]), "r"(b[0]),"r"(b[1]));
}
static __device__ __forceinline__ uint32_t lds32(uint32_t addr){
    uint32_t v; asm volatile("ld.shared.b32 %0, [%1];" : "=r"(v) : "r"(addr)); return v;
}

// one-time: Wlo (bf16 residual) in exact m16n8k16 A-fragment order
__global__ void prep_kernel(const float* __restrict__ W){
    int idx = blockIdx.x * 256 + threadIdx.x;     // 0..8191
    int t = idx >> 5, l = idx & 31;
    int mt = t >> 4, kt = t & 15;
    int g = l >> 2, c = l & 3;
    int m0 = mt * 16 + g, k0 = kt * 16 + c * 2;
    uint32_t r[4];
    #pragma unroll
    for (int q = 0; q < 4; q++){
        int m = m0 + ((q & 1) ? 8 : 0);
        int k = k0 + ((q & 2) ? 8 : 0);
        float w0 = W[m * NREC + k],  w1 = W[m * NREC + k + 1];
        uint16_t l0 = bfu(w0 - bff(bfu(w0)));
        uint16_t l1 = bfu(w1 - bff(bfu(w1)));
        r[q] = (uint32_t)l0 | ((uint32_t)l1 << 16);
    }
    g_wlo[idx] = make_uint4(r[0], r[1], r[2], r[3]);
}

__global__ __launch_bounds__(NT, 1)
void rnn_kernel(const float* __restrict__ x,
                const float* __restrict__ noise,
                const float* __restrict__ W_in,
                const float* __restrict__ W_rec,
                const float* __restrict__ W_out,
                const float* __restrict__ b_out,
                const float* __restrict__ bias,
                float* __restrict__ out, int out_size)
{
    extern __shared__ char sm[];
    const uint32_t sb = smem_u32(sm);
    float* udS = (float*)(sm + UD_OFF);
    float* WoS = (float*)(sm + WOS_OFF);
    float* xb  = (float*)(sm + XB_OFF);

    const int tid = threadIdx.x;
    const int w = tid >> 5, l = tid & 31;
    const int g = l >> 2, c = l & 3;
    const int b0 = blockIdx.x * ROWS;

    // ---- init Whi in SMEM (bf16, swizzled) ----
    for (int i = tid; i < NREC * NREC; i += NT){
        int m = i >> 8, k = i & 255;
        uint16_t h = bfu(W_rec[m * NREC + k]);
        int k16 = k >> 3;
        uint32_t off = (uint32_t)m * 512 + (uint32_t)((k16 ^ (m & 7)) << 4) + (uint32_t)((k & 7) * 2);
        *(uint16_t*)(sm + WHI_OFF + off) = h;
    }
    // zero all r bf16 buffers (r_{-1} = 0)
    for (int i = tid; i < (4 * 4224) / 4; i += NT)
        *(uint32_t*)(sm + RB0H_OFF + i * 4) = 0;
    for (int i = tid; i < NOUT * NREC; i += NT) WoS[i] = W_out[i];
    if (tid < ROWS * NIN){
        int i = tid / NIN, k = tid % NIN;
        xb[i * 12 + k] = x[(size_t)(b0 + i) * TDIM * NIN + k];
    }

    // ---- Wlo A-fragments persist in registers (128 regs, loaded once) ----
    uint4 aloR[16][2];
    #pragma unroll
    for (int kt = 0; kt < 16; kt++)
        #pragma unroll
        for (int mtl = 0; mtl < 2; mtl++)
            aloR[kt][mtl] = g_wlo[((2 * w + mtl) * 16 + kt) * 32 + l];

    float win[NIN];
    #pragma unroll
    for (int k = 0; k < NIN; k++) win[k] = W_in[tid * NIN + k];
    const float bsm = bias[tid];
    const float bo0 = b_out[0], bo1 = b_out[1], bo2 = b_out[2];

    float rold[8];
    #pragma unroll
    for (int s = 0; s < 8; s++) rold[s] = 0.f;
    double l2d = 0.0;

    // coalesced noise prefetch (one step ahead), thread tid <-> column m=tid
    float nzr[ROWS];
    #pragma unroll
    for (int n = 0; n < ROWS; n++)
        nzr[n] = noise[((size_t)(b0 + n) * TDIM + 0) * NREC + tid];

    // ldmatrix lane addressing
    const int rowL = l & 15, hiL = l >> 4, xrL = l & 7;
    uint32_t aBase[2];
    #pragma unroll
    for (int mtl = 0; mtl < 2; mtl++)
        aBase[mtl] = sb + WHI_OFF + (uint32_t)((32 * w + 16 * mtl + rowL) * 512);

    __syncthreads();

    const uint32_t rbH[2] = { sb + RB0H_OFF, sb + RB1H_OFF };
    const uint32_t rbL[2] = { sb + RB0L_OFF, sb + RB1L_OFF };

    for (int ts = 0; ts < TDIM; ts++){
        const int cur = ts & 1, nxt = cur ^ 1;
        const float* xbc = xb + cur * 96;
        float*       xbn = xb + nxt * 96;

        // ---- phase 1: u drive = bias + noise + x@Win^T (coalesced), next-x stage ----
        #pragma unroll
        for (int n = 0; n < ROWS; n++){
            float u = bsm + nzr[n];
            #pragma unroll
            for (int k = 0; k < NIN; k++) u = fmaf(xbc[n * 12 + k], win[k], u);
            udS[n * 260 + tid] = u;
        }
        if (tid < ROWS * NIN){
            int i = tid / NIN, k = tid % NIN;
            int tn = (ts + 1 < TDIM) ? ts + 1 : ts;
            xbn[i * 12 + k] = x[((size_t)(b0 + i) * TDIM + tn) * NIN + k];
        }
        __syncthreads();   // barrier 1: ud visible; prev rbf writes visible

        // prefetch next-step noise (coalesced; latency hidden under MMA)
        {
            int tn = (ts + 1 < TDIM) ? ts + 1 : ts;
            #pragma unroll
            for (int n = 0; n < ROWS; n++)
                nzr[n] = noise[((size_t)(b0 + n) * TDIM + tn) * NREC + tid];
        }

        // ---- phase 2: MMA pipeline over 16 k-tiles ----
        float d[2][4];
        #pragma unroll
        for (int mtl = 0; mtl < 2; mtl++)
            #pragma unroll
            for (int j = 0; j < 4; j++) d[mtl][j] = 0.f;

        const uint32_t bHbase = rbH[cur] + (uint32_t)((l >> 2) * 528 + (l & 3) * 4);
        const uint32_t bLbase = rbL[cur] + (uint32_t)((l >> 2) * 528 + (l & 3) * 4);

        uint32_t bh[2][2], bl[2][2], ah[2][2][4];
        // preload kt = 0
        bh[0][0] = lds32(bHbase);
        bh[0][1] = lds32(bHbase + 16);
        bl[0][0] = lds32(bLbase);
        bl[0][1] = lds32(bLbase + 16);
        #pragma unroll
        for (int mtl = 0; mtl < 2; mtl++)
            ldsm4(ah[0][mtl], aBase[mtl] + (uint32_t)(((0 + hiL) ^ xrL) << 4));

        #pragma unroll
        for (int kt = 0; kt < 16; kt++){
            const int cb = kt & 1, nb = cb ^ 1;
            if (kt < 15){
                uint32_t bo = bHbase + (uint32_t)((kt + 1) * 32);
                bh[nb][0] = lds32(bo);
                bh[nb][1] = lds32(bo + 16);
                uint32_t bo2 = bLbase + (uint32_t)((kt + 1) * 32);
                bl[nb][0] = lds32(bo2);
                bl[nb][1] = lds32(bo2 + 16);
                #pragma unroll
                for (int mtl = 0; mtl < 2; mtl++)
                    ldsm4(ah[nb][mtl], aBase[mtl] + (uint32_t)(((2 * (kt + 1) + hiL) ^ xrL) << 4));
            }
            #pragma unroll
            for (int mtl = 0; mtl < 2; mtl++){
                mma16816(d[mtl], ah[cb][mtl], bh[cb]);                         // Whi*rhi
                mma16816(d[mtl], ah[cb][mtl], bl[cb]);                         // Whi*rlo
                mma16816(d[mtl], (const uint32_t*)&aloR[kt][mtl], bh[cb]);     // Wlo*rhi
            }
        }

        // ---- combine: r_new = 0.8 r + 0.2 relu(v + u) ; publish bf16 hi/lo ----
        float ssum = 0.f;
        #pragma unroll
        for (int mtl = 0; mtl < 2; mtl++)
            #pragma unroll
            for (int j = 0; j < 4; j++){
                int mS = 32 * w + 16 * mtl + g + ((j >> 1) << 3);
                int nS = (c << 1) + (j & 1);
                int s  = mtl * 4 + j;
                float v = d[mtl][j] + udS[nS * 260 + mS];
                float rn = 0.8f * rold[s] + 0.2f * fmaxf(v, 0.f);
                rold[s] = rn;
                uint16_t h  = bfu(rn);
                uint16_t lo = bfu(rn - bff(h));
                uint32_t ro = (uint32_t)(nS * 528 + mS * 2);
                *(uint16_t*)(sm + (rbH[nxt] - sb) + ro) = h;
                *(uint16_t*)(sm + (rbL[nxt] - sb) + ro) = lo;
                ssum = fmaf(rn, rn, ssum);
            }
        l2d += (double)ssum;

        __syncthreads();   // barrier 2: rbf[nxt] published

        // ---- phase 3: z epilogue, warp w -> batch row w (r = hi + lo) ----
        {
            float z0 = 0.f, z1 = 0.f, z2 = 0.f;
            #pragma unroll
            for (int q = 0; q < NREC / 32; q++){
                int m = l + 32 * q;
                uint32_t ro = (uint32_t)(w * 528 + m * 2);
                float ra = bff(*(const uint16_t*)(sm + (rbH[nxt] - sb) + ro))
                         + bff(*(const uint16_t*)(sm + (rbL[nxt] - sb) + ro));
                z0 = fmaf(ra, WoS[m],        z0);
                z1 = fmaf(ra, WoS[256 + m],  z1);
                z2 = fmaf(ra, WoS[512 + m],  z2);
            }
            #pragma unroll
            for (int off = 16; off; off >>= 1){
                z0 += __shfl_down_sync(~0u, z0, off);
                z1 += __shfl_down_sync(~0u, z1, off);
                z2 += __shfl_down_sync(~0u, z2, off);
            }
            if (l == 0){
                size_t ob = ((size_t)(b0 + w) * TDIM + ts) * NOUT;
                out[ob + 0] = z0 + bo0; out[ob + 1] = z1 + bo1; out[ob + 2] = z2 + bo2;
            }
        }
    }

    // ---- deterministic l2 reduction, last-block finalization ----
    __syncthreads();
    double* dd = (double*)(sm + UD_OFF);
    dd[tid] = l2d;
    __syncthreads();
    if (tid == 0){
        double s = 0.0;
        for (int i = 0; i < NT; i++) s += dd[i];
        g_l2p[blockIdx.x] = (float)s;
        __threadfence();
        unsigned int old = atomicInc(&g_ctr, NB - 1);
        if (old == NB - 1){
            __threadfence();
            double tot = 0.0;
            for (int i = 0; i < NB; i++) tot += (double)g_l2p[i];
            out[out_size - 1] = (float)(tot / ((double)TDIM * BATCH * NREC));
        }
    }
}

extern "C" void kernel_launch(void* const* d_in, const int* in_sizes, int n_in,
                              void* d_out, int out_size)
{
    const float* x     = (const float*)d_in[0];
    const float* noise = (const float*)d_in[1];
    const float* W_in  = (const float*)d_in[2];
    const float* W_rec = (const float*)d_in[3];
    const float* W_out = (const float*)d_in[4];
    const float* b_out = (const float*)d_in[5];
    const float* bias  = (const float*)d_in[6];
    float* out = (float*)d_out;

    cudaFuncSetAttribute(rnn_kernel, cudaFuncAttributeMaxDynamicSharedMemorySize, SMEM_BYTES);
    prep_kernel<<<32, 256>>>(W_rec);
    rnn_kernel<<<NB, NT, SMEM_BYTES>>>(x, noise, W_in, W_rec, W_out, b_out, bias, out, out_size);
}